// round 9
// baseline (speedup 1.0000x reference)
#include <cuda_runtime.h>
#include <cuda_bf16.h>
#include <cstdint>
#include <cstddef>

#define Bz   4
#define Nn   2048
#define Dd   64
#define Hh   8
#define VD   124
#define OUTF 992
#define BN   (Bz * Nn)          // 8192
#define INNER 512
#define NROWS (Bz * Hh * Nn)    // 65536 attention rows
#define ATTN_OFF ((size_t)BN * Dd)   // 524288 floats

// ======================= PTX helpers (portable, sm_80+) =====================
__device__ __forceinline__ uint32_t smem_to_u32(const void* smem_ptr) {
    uint32_t addr;
    asm("{ .reg .u64 tmp; cvta.to.shared.u64 tmp, %1; cvt.u32.u64 %0, tmp; }"
        : "=r"(addr) : "l"(smem_ptr));
    return addr;
}

__device__ __forceinline__ void ldsm4(uint32_t* r, uint32_t addr) {
    asm volatile("ldmatrix.sync.aligned.m8n8.x4.shared.b16 {%0,%1,%2,%3}, [%4];"
        : "=r"(r[0]), "=r"(r[1]), "=r"(r[2]), "=r"(r[3]) : "r"(addr));
}

__device__ __forceinline__ void mma16816(float* d, const uint32_t* a,
                                         uint32_t b0, uint32_t b1) {
    asm volatile(
        "mma.sync.aligned.m16n8k16.row.col.f32.bf16.bf16.f32 "
        "{%0,%1,%2,%3}, {%4,%5,%6,%7}, {%8,%9}, {%0,%1,%2,%3};"
        : "+f"(d[0]), "+f"(d[1]), "+f"(d[2]), "+f"(d[3])
        : "r"(a[0]), "r"(a[1]), "r"(a[2]), "r"(a[3]), "r"(b0), "r"(b1));
}

#define CP_ASYNC16(daddr, sptr) \
    asm volatile("cp.async.cg.shared.global [%0], [%1], 16;" \
        :: "r"(daddr), "l"(sptr) : "memory")
#define CP_ASYNC_WAIT_ALL() asm volatile("cp.async.wait_all;" ::: "memory")

// bf16 split (hi + lo)
__device__ __forceinline__ void bf16_split(float v, unsigned short& hs, unsigned short& ls) {
    __nv_bfloat16 bh = __float2bfloat16(v);
    float res = v - __bfloat162float(bh);
    __nv_bfloat16 bl = __float2bfloat16(res);
    hs = __bfloat16_as_ushort(bh);
    ls = __bfloat16_as_ushort(bl);
}

__device__ __forceinline__ void split2(float2 v, uint32_t& hi, uint32_t& lo) {
    unsigned short h0, l0, h1, l1;
    bf16_split(v.x, h0, l0);
    bf16_split(v.y, h1, l1);
    hi = (uint32_t)h0 | ((uint32_t)h1 << 16);
    lo = (uint32_t)l0 | ((uint32_t)l1 << 16);
}

// ======================= scratch (__device__ globals) =======================
__device__ float    g_v[(size_t)BN * VD];
__device__ float    g_o992[(size_t)BN * OUTF];
__device__ float    g_opart[(size_t)4 * BN * OUTF];   // split-k partials
__device__ uint32_t g_qh[(size_t)Bz * Hh * Nn * 32];
__device__ uint32_t g_ql[(size_t)Bz * Hh * Nn * 32];
__device__ uint32_t g_kh[(size_t)Bz * Hh * Nn * 32];
__device__ uint32_t g_kl[(size_t)Bz * Hh * Nn * 32];
__device__ uint32_t g_vth[(size_t)Bz * 32 * 4096];
__device__ uint32_t g_vtl[(size_t)Bz * 32 * 4096];
// per (row, jtile): (log2-domain tile max, tile sum) ; then folded scales
__device__ float2   g_part[(size_t)NROWS * 16];
__device__ float    g_scale[(size_t)NROWS * 16];

// Fused 3-term split-bf16 GEMM core (dots): acc += AhBh + AlBh + AhBl.
// Warp tile 32x64, K-chunk 64, rows padded to 144 bytes.
__device__ __forceinline__ void mma_block3(
    float acc[2][8][4], uint32_t Ah, uint32_t Al, uint32_t Bh, uint32_t Bl,
    int ar, int bc, int lane)
{
    const uint32_t arow  = (uint32_t)(lane & 15);
    const uint32_t acolb = (uint32_t)((lane >> 4) * 16);
    const uint32_t brow  = (uint32_t)((lane & 7) + ((lane >> 4) << 3));
    const uint32_t bcolb = (uint32_t)(((lane >> 3) & 1) * 16);
    #pragma unroll
    for (int ks = 0; ks < 4; ks++) {
        uint32_t ah[2][4], al[2][4], bb[4][4];
        #pragma unroll
        for (int t = 0; t < 2; t++) {
            const uint32_t ro = (uint32_t)(ar + t * 16 + arow) * 144u + ks * 32u + acolb;
            ldsm4(ah[t], Ah + ro);
            ldsm4(al[t], Al + ro);
        }
        #pragma unroll
        for (int p = 0; p < 4; p++)
            ldsm4(bb[p], Bh + (uint32_t)(bc + p * 16 + brow) * 144u + ks * 32u + bcolb);
        #pragma unroll
        for (int t = 0; t < 2; t++)
            #pragma unroll
            for (int p = 0; p < 4; p++) {
                mma16816(acc[t][2 * p],     ah[t], bb[p][0], bb[p][1]);
                mma16816(acc[t][2 * p + 1], ah[t], bb[p][2], bb[p][3]);
                mma16816(acc[t][2 * p],     al[t], bb[p][0], bb[p][1]);
                mma16816(acc[t][2 * p + 1], al[t], bb[p][2], bb[p][3]);
            }
        #pragma unroll
        for (int p = 0; p < 4; p++)
            ldsm4(bb[p], Bl + (uint32_t)(bc + p * 16 + brow) * 144u + ks * 32u + bcolb);
        #pragma unroll
        for (int t = 0; t < 2; t++)
            #pragma unroll
            for (int p = 0; p < 4; p++) {
                mma16816(acc[t][2 * p],     ah[t], bb[p][0], bb[p][1]);
                mma16816(acc[t][2 * p + 1], ah[t], bb[p][2], bb[p][3]);
            }
    }
}

// ---------------------------------------------------------------------------
// Kernel 1: qk = x @ W_qk^T -> split-bf16 q/k
// ---------------------------------------------------------------------------
__global__ __launch_bounds__(256) void qk_proj_kernel(
    const float* __restrict__ x, const float* __restrict__ Wqk)
{
    __shared__ float As[16][68];
    __shared__ float Bs[16][68];
    const int tid = threadIdx.x;
    const int tx = tid & 15, ty = tid >> 4;
    const int row0 = blockIdx.x * 64;
    const int col0 = blockIdx.y * 64;

    float acc[4][4] = {};
    for (int k0 = 0; k0 < 64; k0 += 16) {
        const int r  = tid >> 2;
        const int kq = (tid & 3) << 2;
        float4 a = *(const float4*)&x[(size_t)(row0 + r) * Dd + k0 + kq];
        As[kq + 0][r] = a.x; As[kq + 1][r] = a.y;
        As[kq + 2][r] = a.z; As[kq + 3][r] = a.w;
        float4 b = *(const float4*)&Wqk[(size_t)(col0 + r) * Dd + k0 + kq];
        Bs[kq + 0][r] = b.x; Bs[kq + 1][r] = b.y;
        Bs[kq + 2][r] = b.z; Bs[kq + 3][r] = b.w;
        __syncthreads();
        #pragma unroll
        for (int kk = 0; kk < 16; kk++) {
            float av[4], bv[4];
            *(float4*)av = *(const float4*)&As[kk][ty * 4];
            *(float4*)bv = *(const float4*)&Bs[kk][tx * 4];
            #pragma unroll
            for (int m = 0; m < 4; m++)
                #pragma unroll
                for (int n = 0; n < 4; n++)
                    acc[m][n] = fmaf(av[m], bv[n], acc[m][n]);
        }
        __syncthreads();
    }

    const bool is_q = (col0 < INNER);
    const int  cb   = is_q ? col0 : (col0 - INNER);
    const int  h    = cb >> 6;
    uint32_t* dh = is_q ? g_qh : g_kh;
    uint32_t* dl = is_q ? g_ql : g_kl;
    #pragma unroll
    for (int m = 0; m < 4; m++) {
        const int r  = row0 + ty * 4 + m;
        const int b  = r / Nn;
        const int nn = r % Nn;
        const size_t base = ((size_t)(b * Hh + h) * Nn + nn) * 32 + tx * 2;
        uint32_t h01, l01, h23, l23;
        split2(make_float2(acc[m][0], acc[m][1]), h01, l01);
        split2(make_float2(acc[m][2], acc[m][3]), h23, l23);
        dh[base]     = h01;
        dh[base + 1] = h23;
        dl[base]     = l01;
        dl[base + 1] = l23;
    }
}

// ---------------------------------------------------------------------------
// Kernel 2: conv value (fp32 -> g_v)
// ---------------------------------------------------------------------------
__global__ __launch_bounds__(256) void conv_kernel(
    const float* __restrict__ x,
    const float* __restrict__ w1, const float* __restrict__ b1,
    const float* __restrict__ w2, const float* __restrict__ b2)
{
    __shared__ float sx[8][64];
    __shared__ float sh1[8][80];
    const int w    = threadIdx.x >> 5;
    const int lane = threadIdx.x & 31;
    const int row  = blockIdx.x * 8 + w;

    sx[w][lane]      = x[(size_t)row * Dd + lane];
    sx[w][lane + 32] = x[(size_t)row * Dd + 32 + lane];
    __syncwarp();

    for (int idx = lane; idx < 80; idx += 32) {
        const int c = idx / 40, p = idx % 40;
        float s = b1[c];
        #pragma unroll
        for (int t = 0; t < 25; t++)
            s = fmaf(sx[w][p + t], w1[c * 25 + t], s);
        sh1[w][idx] = s;
    }
    __syncwarp();

    for (int idx = lane; idx < VD; idx += 32) {
        const int c2 = idx / 31, p = idx % 31;
        float s = b2[c2];
        #pragma unroll
        for (int c1 = 0; c1 < 2; c1++)
            #pragma unroll
            for (int t = 0; t < 10; t++)
                s = fmaf(sh1[w][c1 * 40 + p + t], w2[(c2 * 2 + c1) * 10 + t], s);
        g_v[(size_t)row * VD + idx] = s;
    }
}

// ---------------------------------------------------------------------------
// Kernel 2b: V -> transposed split-bf16 chunk tiles
// ---------------------------------------------------------------------------
__global__ __launch_bounds__(256) void vconv_kernel()
{
    const int blk = blockIdx.x;
    const int b = blk >> 5, jc = blk & 31;
    const int j0 = jc * 64;
    unsigned short* oh = (unsigned short*)g_vth;
    unsigned short* ol = (unsigned short*)g_vtl;
    for (int e = threadIdx.x; e < 8192; e += 256) {
        const int c = e >> 6, jj = e & 63;
        float v = (c < VD) ? g_v[((size_t)b * Nn + j0 + jj) * VD + c] : 0.0f;
        unsigned short hh, ll;
        bf16_split(v, hh, ll);
        const size_t o = ((size_t)blk * 128 + c) * 64 + jj;
        oh[o] = hh;
        ol[o] = ll;
    }
}

// ---------------------------------------------------------------------------
// Kernel 3: dots; Q resident, loops 4 j-tiles of 128 with K double-buffered
// via cp.async. Log2-domain single-exp2 softmax epilogue per tile.
// grid (4 jq, 16 i, 32 bh) = 2048 CTAs, 256 thr, 2 CTAs/SM.
// smem 110592: Qh 0  Ql 18432  K s0: 36864/55296  K s1: 73728/92160
// ---------------------------------------------------------------------------
__global__ __launch_bounds__(256, 2) void dots_mma_kernel(float* __restrict__ attn)
{
    extern __shared__ char sm[];
    __shared__ float smax[128][2];
    __shared__ float ssum[128][2];
    __shared__ float s_mjt[128];
    const int tid = threadIdx.x, lane = tid & 31, wid = tid >> 5;
    const int bh = blockIdx.z;
    const int i0 = blockIdx.y * 128;
    const int jq = blockIdx.x;           // 0..3, j-range jq*512 .. +512
    const uint32_t sb = smem_to_u32(sm);

    // Q load (once)
    const char* qh = (const char*)(g_qh + ((size_t)bh * Nn + i0) * 32);
    const char* ql = (const char*)(g_ql + ((size_t)bh * Nn + i0) * 32);
    for (int i = tid; i < 1024; i += 256) {
        const int row = i >> 3, q = i & 7;
        const uint32_t off = (uint32_t)(row * 144 + q * 16);
        CP_ASYNC16(sb + off, qh + i * 16);
        CP_ASYNC16(sb + 18432 + off, ql + i * 16);
    }

    auto issueK = [&](int jt_abs, int st) {
        const char* kh = (const char*)(g_kh + ((size_t)bh * Nn + jt_abs * 128) * 32);
        const char* kl = (const char*)(g_kl + ((size_t)bh * Nn + jt_abs * 128) * 32);
        const uint32_t base = sb + 36864u + (uint32_t)st * 36864u;
        for (int i = tid; i < 1024; i += 256) {
            const int row = i >> 3, q = i & 7;
            const uint32_t off = (uint32_t)(row * 144 + q * 16);
            CP_ASYNC16(base + off, kh + i * 16);
            CP_ASYNC16(base + 18432 + off, kl + i * 16);
        }
    };

    issueK(jq * 4, 0);
    CP_ASYNC_WAIT_ALL();
    __syncthreads();

    const int ar = (wid >> 1) * 32, bc = (wid & 1) * 64;
    float* C = attn + (size_t)bh * Nn * Nn;
    const float S = 0.125f * 1.4426950408889634f;  // scale * log2(e)

    for (int jt = 0; jt < 4; jt++) {
        const int st = jt & 1;
        const int pi = jq * 4 + jt;      // absolute j-tile index (0..15)
        if (jt < 3) issueK(pi + 1, 1 - st);

        float acc[2][8][4] = {};
        mma_block3(acc, sb, sb + 18432,
                   sb + 36864 + st * 36864, sb + 55296 + st * 36864,
                   ar, bc, lane);

        #pragma unroll
        for (int t = 0; t < 2; t++)
            #pragma unroll
            for (int nt = 0; nt < 8; nt++)
                #pragma unroll
                for (int e = 0; e < 4; e++)
                    acc[t][nt][e] *= S;

        // per-row max over this 128-col j-tile
        #pragma unroll
        for (int t = 0; t < 2; t++) {
            float mA = -1e30f, mB = -1e30f;
            #pragma unroll
            for (int nt = 0; nt < 8; nt++) {
                mA = fmaxf(mA, fmaxf(acc[t][nt][0], acc[t][nt][1]));
                mB = fmaxf(mB, fmaxf(acc[t][nt][2], acc[t][nt][3]));
            }
            mA = fmaxf(mA, __shfl_xor_sync(0xffffffffu, mA, 1));
            mA = fmaxf(mA, __shfl_xor_sync(0xffffffffu, mA, 2));
            mB = fmaxf(mB, __shfl_xor_sync(0xffffffffu, mB, 1));
            mB = fmaxf(mB, __shfl_xor_sync(0xffffffffu, mB, 2));
            if ((lane & 3) == 0) {
                const int rl = ar + t * 16 + (lane >> 2);
                smax[rl][wid & 1]     = mA;
                smax[rl + 8][wid & 1] = mB;
            }
        }
        __syncthreads();
        if (tid < 128) s_mjt[tid] = fmaxf(smax[tid][0], smax[tid][1]);
        __syncthreads();

        // single exp2 per element: write e and accumulate tile sums
        #pragma unroll
        for (int t = 0; t < 2; t++) {
            const int rl = ar + t * 16 + (lane >> 2);
            const float m0 = s_mjt[rl], m1 = s_mjt[rl + 8];
            const int r0 = i0 + rl;
            float sA = 0.f, sB = 0.f;
            #pragma unroll
            for (int nt = 0; nt < 8; nt++) {
                const int c0 = pi * 128 + bc + nt * 8 + (lane & 3) * 2;
                const float e0 = exp2f(acc[t][nt][0] - m0);
                const float e1 = exp2f(acc[t][nt][1] - m0);
                const float e2 = exp2f(acc[t][nt][2] - m1);
                const float e3 = exp2f(acc[t][nt][3] - m1);
                *(float2*)&C[(size_t)r0 * Nn + c0]       = make_float2(e0, e1);
                *(float2*)&C[(size_t)(r0 + 8) * Nn + c0] = make_float2(e2, e3);
                sA += e0 + e1;
                sB += e2 + e3;
            }
            sA += __shfl_xor_sync(0xffffffffu, sA, 1);
            sA += __shfl_xor_sync(0xffffffffu, sA, 2);
            sB += __shfl_xor_sync(0xffffffffu, sB, 1);
            sB += __shfl_xor_sync(0xffffffffu, sB, 2);
            if ((lane & 3) == 0) {
                ssum[rl][wid & 1]     = sA;
                ssum[rl + 8][wid & 1] = sB;
            }
        }
        __syncthreads();
        if (tid < 128)
            g_part[((size_t)bh * Nn + i0 + tid) * 16 + pi] =
                make_float2(s_mjt[tid], ssum[tid][0] + ssum[tid][1]);
        CP_ASYNC_WAIT_ALL();
        __syncthreads();
    }
}

// ---------------------------------------------------------------------------
// Kernel 3b: fold partials -> per-(row,jt) scale = exp2(m_jt - m_row)/rowsum
// ---------------------------------------------------------------------------
__global__ __launch_bounds__(256) void rowstat_kernel()
{
    const int row = blockIdx.x * 256 + threadIdx.x;
    float2 p[16];
    #pragma unroll
    for (int t = 0; t < 16; t++) p[t] = g_part[(size_t)row * 16 + t];
    float m = -1e30f;
    #pragma unroll
    for (int t = 0; t < 16; t++) m = fmaxf(m, p[t].x);
    float s = 0.f;
    #pragma unroll
    for (int t = 0; t < 16; t++) s += p[t].y * exp2f(p[t].x - m);
    const float inv = 1.0f / s;
    #pragma unroll
    for (int t = 0; t < 16; t++)
        g_scale[(size_t)row * 16 + t] = exp2f(p[t].x - m) * inv;
}

// ---------------------------------------------------------------------------
// Kernel 5: AV with split-k=4. Each CTA handles 8 chunks (k-slice of 512),
// A loaded gmem->registers in fragment layout, scaled + written back to attn,
// bf16-split in regs, MMA vs cp.async double-buffered V^T. Partials -> g_opart.
// grid (16 i, 4 ks, 32 bh) = 2048 CTAs, 256 thr, 2 CTAs/SM.
// smem 75776: Bh0 0  Bl0 18432  Bh1 36864  Bl1 55296  scales 73728 (2KB)
// ---------------------------------------------------------------------------
__global__ __launch_bounds__(256, 2) void av_mma_kernel(float* __restrict__ attn)
{
    extern __shared__ char sm[];
    const int tid = threadIdx.x, lane = tid & 31, wid = tid >> 5;
    const int bh = blockIdx.z;
    const int b = bh >> 3, h = bh & 7;
    const int i0 = blockIdx.x * 128;
    const int ks = blockIdx.y;          // k-slice 0..3
    const int ic0 = ks * 8;
    const uint32_t sb = smem_to_u32(sm);
    float* s_scale = (float*)(sm + 73728);   // [128 rows][4 jts]

    for (int i = tid; i < 512; i += 256)
        s_scale[i] = g_scale[((size_t)bh * Nn + i0 + (i >> 2)) * 16 + ks * 4 + (i & 3)];

    auto issueB = [&](int ic2, int st2) {
        const char* vh = (const char*)(g_vth + (size_t)(b * 32 + ic2) * 4096);
        const char* vl = (const char*)(g_vtl + (size_t)(b * 32 + ic2) * 4096);
        const uint32_t base = sb + (uint32_t)st2 * 36864u;
        for (int i = tid; i < 1024; i += 256) {
            const int row = i >> 3, q = i & 7;
            const uint32_t off = (uint32_t)(row * 144 + q * 16);
            CP_ASYNC16(base + off, vh + i * 16);
            CP_ASYNC16(base + 18432 + off, vl + i * 16);
        }
    };

    issueB(ic0, 0);
    CP_ASYNC_WAIT_ALL();
    __syncthreads();

    float* A0 = attn + ((size_t)bh * Nn + i0) * Nn;
    const int ar = wid * 16;
    const int r = lane >> 2, c0 = (lane & 3) * 2;
    const uint32_t brow  = (uint32_t)((lane & 7) + ((lane >> 4) << 3));
    const uint32_t bcolb = (uint32_t)(((lane >> 3) & 1) * 16);

    float* Ar0 = A0 + (size_t)(ar + r) * Nn;
    float* Ar8 = Ar0 + 8 * Nn;

    float acc[16][4] = {};
    for (int ii = 0; ii < 8; ii++) {
        const int ic = ic0 + ii;
        const int st = ii & 1;
        const int jl = (ic >> 1) - ks * 4;   // local j-tile 0..3
        if (ii + 1 < 8) issueB(ic + 1, 1 - st);

        const uint32_t Bh = sb + (uint32_t)st * 36864u;
        const uint32_t Bl = Bh + 18432u;
        const float sc0 = s_scale[(ar + r) * 4 + jl];
        const float sc1 = s_scale[(ar + r + 8) * 4 + jl];
        float* a0 = Ar0 + ic * 64;
        float* a8 = Ar8 + ic * 64;

        #pragma unroll
        for (int kh = 0; kh < 2; kh++) {
            float2 vv[2][4];
            #pragma unroll
            for (int k2 = 0; k2 < 2; k2++) {
                const int kc = (kh * 2 + k2) * 16 + c0;
                vv[k2][0] = *(const float2*)(a0 + kc);
                vv[k2][1] = *(const float2*)(a8 + kc);
                vv[k2][2] = *(const float2*)(a0 + kc + 8);
                vv[k2][3] = *(const float2*)(a8 + kc + 8);
            }
            #pragma unroll
            for (int k2 = 0; k2 < 2; k2++) {
                const int ksl = kh * 2 + k2;
                float2 v00 = vv[k2][0], v10 = vv[k2][1];
                float2 v01 = vv[k2][2], v11 = vv[k2][3];
                v00.x *= sc0; v00.y *= sc0; v01.x *= sc0; v01.y *= sc0;
                v10.x *= sc1; v10.y *= sc1; v11.x *= sc1; v11.y *= sc1;
                const int kc = ksl * 16 + c0;
                *(float2*)(a0 + kc)     = v00;
                *(float2*)(a8 + kc)     = v10;
                *(float2*)(a0 + kc + 8) = v01;
                *(float2*)(a8 + kc + 8) = v11;
                uint32_t ah[4], al[4];
                split2(v00, ah[0], al[0]);
                split2(v10, ah[1], al[1]);
                split2(v01, ah[2], al[2]);
                split2(v11, ah[3], al[3]);
                #pragma unroll
                for (int p = 0; p < 8; p++) {
                    uint32_t bb[4];
                    ldsm4(bb, Bh + (uint32_t)(p * 16 + brow) * 144u + ksl * 32u + bcolb);
                    mma16816(acc[2 * p],     ah, bb[0], bb[1]);
                    mma16816(acc[2 * p + 1], ah, bb[2], bb[3]);
                    mma16816(acc[2 * p],     al, bb[0], bb[1]);
                    mma16816(acc[2 * p + 1], al, bb[2], bb[3]);
                }
                #pragma unroll
                for (int p = 0; p < 8; p++) {
                    uint32_t bb[4];
                    ldsm4(bb, Bl + (uint32_t)(p * 16 + brow) * 144u + ksl * 32u + bcolb);
                    mma16816(acc[2 * p],     ah, bb[0], bb[1]);
                    mma16816(acc[2 * p + 1], ah, bb[2], bb[3]);
                }
            }
        }
        CP_ASYNC_WAIT_ALL();
        __syncthreads();
    }

    float* O = g_opart + ((size_t)ks * BN + (size_t)b * Nn) * OUTF + (size_t)h * VD;
    const int r0 = i0 + ar + r;
    #pragma unroll
    for (int nt = 0; nt < 16; nt++) {
        const int cc = nt * 8 + c0;
        if (cc < VD) {
            *(float2*)&O[(size_t)r0 * OUTF + cc] =
                make_float2(acc[nt][0], acc[nt][1]);
            *(float2*)&O[(size_t)(r0 + 8) * OUTF + cc] =
                make_float2(acc[nt][2], acc[nt][3]);
        }
    }
}

// ---------------------------------------------------------------------------
// Kernel 5b: reduce 4 split-k partials -> g_o992
// ---------------------------------------------------------------------------
__global__ __launch_bounds__(256) void oreduce_kernel()
{
    const size_t idx = (size_t)blockIdx.x * 256 + threadIdx.x;  // float4 units
    const size_t STRIDE = (size_t)BN * OUTF / 4;
    const float4* p = (const float4*)g_opart;
    float4 a = p[idx];
    float4 b = p[idx + STRIDE];
    float4 c = p[idx + 2 * STRIDE];
    float4 d = p[idx + 3 * STRIDE];
    ((float4*)g_o992)[idx] = make_float4(a.x + b.x + c.x + d.x,
                                         a.y + b.y + c.y + d.y,
                                         a.z + b.z + c.z + d.z,
                                         a.w + b.w + c.w + d.w);
}

// ---------------------------------------------------------------------------
// Kernel 6: out = out992 @ W_out^T + b_out
// ---------------------------------------------------------------------------
__global__ __launch_bounds__(256) void outproj_kernel(
    const float* __restrict__ Wout, const float* __restrict__ bout,
    float* __restrict__ out)
{
    __shared__ float As[16][68];
    __shared__ float Bs[16][68];
    const int i0 = blockIdx.x * 64;
    const int tid = threadIdx.x;
    const int tx = tid & 15, ty = tid >> 4;

    float acc[4][4] = {};
    for (int k0 = 0; k0 < OUTF; k0 += 16) {
        const int r  = tid >> 2;
        const int kq = (tid & 3) << 2;
        float4 a = *(const float4*)&g_o992[(size_t)(i0 + r) * OUTF + k0 + kq];
        As[kq + 0][r] = a.x; As[kq + 1][r] = a.y;
        As[kq + 2][r] = a.z; As[kq + 3][r] = a.w;
        float4 w = *(const float4*)&Wout[(size_t)r * OUTF + k0 + kq];
        Bs[kq + 0][r] = w.x; Bs[kq + 1][r] = w.y;
        Bs[kq + 2][r] = w.z; Bs[kq + 3][r] = w.w;
        __syncthreads();
        #pragma unroll
        for (int kk = 0; kk < 16; kk++) {
            float av[4], bv[4];
            *(float4*)av = *(const float4*)&As[kk][ty * 4];
            *(float4*)bv = *(const float4*)&Bs[kk][tx * 4];
            #pragma unroll
            for (int m = 0; m < 4; m++)
                #pragma unroll
                for (int n = 0; n < 4; n++)
                    acc[m][n] = fmaf(av[m], bv[n], acc[m][n]);
        }
        __syncthreads();
    }

    #pragma unroll
    for (int m = 0; m < 4; m++) {
        const int r = i0 + ty * 4 + m;
        float4 v = make_float4(acc[m][0] + bout[tx * 4 + 0],
                               acc[m][1] + bout[tx * 4 + 1],
                               acc[m][2] + bout[tx * 4 + 2],
                               acc[m][3] + bout[tx * 4 + 3]);
        *(float4*)&out[(size_t)r * Dd + tx * 4] = v;
    }
}

// ---------------------------------------------------------------------------
extern "C" void kernel_launch(void* const* d_in, const int* in_sizes, int n_in,
                              void* d_out, int out_size)
{
    const float* x    = (const float*)d_in[0];
    const float* Wqk  = (const float*)d_in[1];
    const float* w1   = (const float*)d_in[2];
    const float* b1   = (const float*)d_in[3];
    const float* w2   = (const float*)d_in[4];
    const float* b2   = (const float*)d_in[5];
    const float* Wout = (const float*)d_in[6];
    const float* bout = (const float*)d_in[7];

    float* out  = (float*)d_out;
    float* attn = out + ATTN_OFF;

    cudaFuncSetAttribute(dots_mma_kernel,
                         cudaFuncAttributeMaxDynamicSharedMemorySize, 110592);
    cudaFuncSetAttribute(av_mma_kernel,
                         cudaFuncAttributeMaxDynamicSharedMemorySize, 75776);

    qk_proj_kernel<<<dim3(BN / 64, 1024 / 64), 256>>>(x, Wqk);
    conv_kernel<<<BN / 8, 256>>>(x, w1, b1, w2, b2);
    vconv_kernel<<<Bz * 32, 256>>>();
    dots_mma_kernel<<<dim3(4, Nn / 128, Bz * Hh), 256, 110592>>>(attn);
    rowstat_kernel<<<NROWS / 256, 256>>>();
    av_mma_kernel<<<dim3(Nn / 128, 4, Bz * Hh), 256, 75776>>>(attn);
    oreduce_kernel<<<(int)((size_t)BN * OUTF / 4 / 256), 256>>>();
    outproj_kernel<<<BN / 64, 256>>>(Wout, bout, out);
}

// round 11
// speedup vs baseline: 1.4349x; 1.4349x over previous
#include <cuda_runtime.h>
#include <cuda_bf16.h>
#include <cstdint>
#include <cstddef>

#define Bz   4
#define Nn   2048
#define Dd   64
#define Hh   8
#define VD   124
#define OUTF 992
#define BN   (Bz * Nn)          // 8192
#define INNER 512
#define NROWS (Bz * Hh * Nn)    // 65536 attention rows
#define ATTN_OFF ((size_t)BN * Dd)   // 524288 floats

// ======================= PTX helpers (portable, sm_80+) =====================
__device__ __forceinline__ uint32_t smem_to_u32(const void* smem_ptr) {
    uint32_t addr;
    asm("{ .reg .u64 tmp; cvta.to.shared.u64 tmp, %1; cvt.u32.u64 %0, tmp; }"
        : "=r"(addr) : "l"(smem_ptr));
    return addr;
}

__device__ __forceinline__ void ldsm4(uint32_t* r, uint32_t addr) {
    asm volatile("ldmatrix.sync.aligned.m8n8.x4.shared.b16 {%0,%1,%2,%3}, [%4];"
        : "=r"(r[0]), "=r"(r[1]), "=r"(r[2]), "=r"(r[3]) : "r"(addr));
}

__device__ __forceinline__ void mma16816(float* d, const uint32_t* a,
                                         uint32_t b0, uint32_t b1) {
    asm volatile(
        "mma.sync.aligned.m16n8k16.row.col.f32.bf16.bf16.f32 "
        "{%0,%1,%2,%3}, {%4,%5,%6,%7}, {%8,%9}, {%0,%1,%2,%3};"
        : "+f"(d[0]), "+f"(d[1]), "+f"(d[2]), "+f"(d[3])
        : "r"(a[0]), "r"(a[1]), "r"(a[2]), "r"(a[3]), "r"(b0), "r"(b1));
}

#define CP_ASYNC16(daddr, sptr) \
    asm volatile("cp.async.cg.shared.global [%0], [%1], 16;" \
        :: "r"(daddr), "l"(sptr) : "memory")
#define CP_ASYNC_WAIT_ALL() asm volatile("cp.async.wait_all;" ::: "memory")

// bf16 split (hi + lo)
__device__ __forceinline__ void bf16_split(float v, unsigned short& hs, unsigned short& ls) {
    __nv_bfloat16 bh = __float2bfloat16(v);
    float res = v - __bfloat162float(bh);
    __nv_bfloat16 bl = __float2bfloat16(res);
    hs = __bfloat16_as_ushort(bh);
    ls = __bfloat16_as_ushort(bl);
}

__device__ __forceinline__ void split2(float2 v, uint32_t& hi, uint32_t& lo) {
    unsigned short h0, l0, h1, l1;
    bf16_split(v.x, h0, l0);
    bf16_split(v.y, h1, l1);
    hi = (uint32_t)h0 | ((uint32_t)h1 << 16);
    lo = (uint32_t)l0 | ((uint32_t)l1 << 16);
}

// ======================= scratch (__device__ globals) =======================
__device__ float    g_v[(size_t)BN * VD];
__device__ float    g_o992[(size_t)BN * OUTF];
__device__ uint32_t g_qh[(size_t)Bz * Hh * Nn * 32];
__device__ uint32_t g_ql[(size_t)Bz * Hh * Nn * 32];
__device__ uint32_t g_kh[(size_t)Bz * Hh * Nn * 32];
__device__ uint32_t g_kl[(size_t)Bz * Hh * Nn * 32];
__device__ uint32_t g_vth[(size_t)Bz * 32 * 4096];
__device__ uint32_t g_vtl[(size_t)Bz * 32 * 4096];
// per (row, jtile): (log2-domain tile max, tile sum) ; then folded scales
__device__ float2   g_part[(size_t)NROWS * 16];
__device__ float    g_scale[(size_t)NROWS * 16];

// Fused 3-term split-bf16 GEMM core (dots): acc += AhBh + AlBh + AhBl.
// Warp tile 32x64, K-chunk 64, rows padded to 144 bytes.
__device__ __forceinline__ void mma_block3(
    float acc[2][8][4], uint32_t Ah, uint32_t Al, uint32_t Bh, uint32_t Bl,
    int ar, int bc, int lane)
{
    const uint32_t arow  = (uint32_t)(lane & 15);
    const uint32_t acolb = (uint32_t)((lane >> 4) * 16);
    const uint32_t brow  = (uint32_t)((lane & 7) + ((lane >> 4) << 3));
    const uint32_t bcolb = (uint32_t)(((lane >> 3) & 1) * 16);
    #pragma unroll
    for (int ks = 0; ks < 4; ks++) {
        uint32_t ah[2][4], al[2][4], bb[4][4];
        #pragma unroll
        for (int t = 0; t < 2; t++) {
            const uint32_t ro = (uint32_t)(ar + t * 16 + arow) * 144u + ks * 32u + acolb;
            ldsm4(ah[t], Ah + ro);
            ldsm4(al[t], Al + ro);
        }
        #pragma unroll
        for (int p = 0; p < 4; p++)
            ldsm4(bb[p], Bh + (uint32_t)(bc + p * 16 + brow) * 144u + ks * 32u + bcolb);
        #pragma unroll
        for (int t = 0; t < 2; t++)
            #pragma unroll
            for (int p = 0; p < 4; p++) {
                mma16816(acc[t][2 * p],     ah[t], bb[p][0], bb[p][1]);
                mma16816(acc[t][2 * p + 1], ah[t], bb[p][2], bb[p][3]);
                mma16816(acc[t][2 * p],     al[t], bb[p][0], bb[p][1]);
                mma16816(acc[t][2 * p + 1], al[t], bb[p][2], bb[p][3]);
            }
        #pragma unroll
        for (int p = 0; p < 4; p++)
            ldsm4(bb[p], Bl + (uint32_t)(bc + p * 16 + brow) * 144u + ks * 32u + bcolb);
        #pragma unroll
        for (int t = 0; t < 2; t++)
            #pragma unroll
            for (int p = 0; p < 4; p++) {
                mma16816(acc[t][2 * p],     ah[t], bb[p][0], bb[p][1]);
                mma16816(acc[t][2 * p + 1], ah[t], bb[p][2], bb[p][3]);
            }
    }
}

// ---------------------------------------------------------------------------
// Kernel 1: qk = x @ W_qk^T -> split-bf16 q/k
// ---------------------------------------------------------------------------
__global__ __launch_bounds__(256) void qk_proj_kernel(
    const float* __restrict__ x, const float* __restrict__ Wqk)
{
    __shared__ float As[16][68];
    __shared__ float Bs[16][68];
    const int tid = threadIdx.x;
    const int tx = tid & 15, ty = tid >> 4;
    const int row0 = blockIdx.x * 64;
    const int col0 = blockIdx.y * 64;

    float acc[4][4] = {};
    for (int k0 = 0; k0 < 64; k0 += 16) {
        const int r  = tid >> 2;
        const int kq = (tid & 3) << 2;
        float4 a = *(const float4*)&x[(size_t)(row0 + r) * Dd + k0 + kq];
        As[kq + 0][r] = a.x; As[kq + 1][r] = a.y;
        As[kq + 2][r] = a.z; As[kq + 3][r] = a.w;
        float4 b = *(const float4*)&Wqk[(size_t)(col0 + r) * Dd + k0 + kq];
        Bs[kq + 0][r] = b.x; Bs[kq + 1][r] = b.y;
        Bs[kq + 2][r] = b.z; Bs[kq + 3][r] = b.w;
        __syncthreads();
        #pragma unroll
        for (int kk = 0; kk < 16; kk++) {
            float av[4], bv[4];
            *(float4*)av = *(const float4*)&As[kk][ty * 4];
            *(float4*)bv = *(const float4*)&Bs[kk][tx * 4];
            #pragma unroll
            for (int m = 0; m < 4; m++)
                #pragma unroll
                for (int n = 0; n < 4; n++)
                    acc[m][n] = fmaf(av[m], bv[n], acc[m][n]);
        }
        __syncthreads();
    }

    const bool is_q = (col0 < INNER);
    const int  cb   = is_q ? col0 : (col0 - INNER);
    const int  h    = cb >> 6;
    uint32_t* dh = is_q ? g_qh : g_kh;
    uint32_t* dl = is_q ? g_ql : g_kl;
    #pragma unroll
    for (int m = 0; m < 4; m++) {
        const int r  = row0 + ty * 4 + m;
        const int b  = r / Nn;
        const int nn = r % Nn;
        const size_t base = ((size_t)(b * Hh + h) * Nn + nn) * 32 + tx * 2;
        uint32_t h01, l01, h23, l23;
        split2(make_float2(acc[m][0], acc[m][1]), h01, l01);
        split2(make_float2(acc[m][2], acc[m][3]), h23, l23);
        dh[base]     = h01;
        dh[base + 1] = h23;
        dl[base]     = l01;
        dl[base + 1] = l23;
    }
}

// ---------------------------------------------------------------------------
// Kernel 2: conv value (fp32 -> g_v)
// ---------------------------------------------------------------------------
__global__ __launch_bounds__(256) void conv_kernel(
    const float* __restrict__ x,
    const float* __restrict__ w1, const float* __restrict__ b1,
    const float* __restrict__ w2, const float* __restrict__ b2)
{
    __shared__ float sx[8][64];
    __shared__ float sh1[8][80];
    const int w    = threadIdx.x >> 5;
    const int lane = threadIdx.x & 31;
    const int row  = blockIdx.x * 8 + w;

    sx[w][lane]      = x[(size_t)row * Dd + lane];
    sx[w][lane + 32] = x[(size_t)row * Dd + 32 + lane];
    __syncwarp();

    for (int idx = lane; idx < 80; idx += 32) {
        const int c = idx / 40, p = idx % 40;
        float s = b1[c];
        #pragma unroll
        for (int t = 0; t < 25; t++)
            s = fmaf(sx[w][p + t], w1[c * 25 + t], s);
        sh1[w][idx] = s;
    }
    __syncwarp();

    for (int idx = lane; idx < VD; idx += 32) {
        const int c2 = idx / 31, p = idx % 31;
        float s = b2[c2];
        #pragma unroll
        for (int c1 = 0; c1 < 2; c1++)
            #pragma unroll
            for (int t = 0; t < 10; t++)
                s = fmaf(sh1[w][c1 * 40 + p + t], w2[(c2 * 2 + c1) * 10 + t], s);
        g_v[(size_t)row * VD + idx] = s;
    }
}

// ---------------------------------------------------------------------------
// Kernel 2b: V -> transposed split-bf16 chunk tiles
// ---------------------------------------------------------------------------
__global__ __launch_bounds__(256) void vconv_kernel()
{
    const int blk = blockIdx.x;
    const int b = blk >> 5, jc = blk & 31;
    const int j0 = jc * 64;
    unsigned short* oh = (unsigned short*)g_vth;
    unsigned short* ol = (unsigned short*)g_vtl;
    for (int e = threadIdx.x; e < 8192; e += 256) {
        const int c = e >> 6, jj = e & 63;
        float v = (c < VD) ? g_v[((size_t)b * Nn + j0 + jj) * VD + c] : 0.0f;
        unsigned short hh, ll;
        bf16_split(v, hh, ll);
        const size_t o = ((size_t)blk * 128 + c) * 64 + jj;
        oh[o] = hh;
        ol[o] = ll;
    }
}

// ---------------------------------------------------------------------------
// Kernel 3: dots; j-tile 256 (two 128-col halves off one Q load).
// Log2-domain single-exp2 softmax epilogue; inline cross-warp max combine
// (5 barriers per CTA instead of 8).
// grid (8,16,32), 256 threads, 2 CTAs/SM. dyn smem = 110592 B.
// ---------------------------------------------------------------------------
__global__ __launch_bounds__(256, 2) void dots_mma_kernel(float* __restrict__ attn)
{
    extern __shared__ char sm[];
    __shared__ float smax[128][2];
    __shared__ float ssum[128][2];
    const int tid = threadIdx.x, lane = tid & 31, wid = tid >> 5;
    const int bh = blockIdx.z;
    const int i0 = blockIdx.y * 128, j0 = blockIdx.x * 256;

    const uint4* qh = (const uint4*)(g_qh + ((size_t)bh * Nn + i0) * 32);
    const uint4* ql = (const uint4*)(g_ql + ((size_t)bh * Nn + i0) * 32);
    const uint4* kh = (const uint4*)(g_kh + ((size_t)bh * Nn + j0) * 32);
    const uint4* kl = (const uint4*)(g_kl + ((size_t)bh * Nn + j0) * 32);
    for (int i = tid; i < 1024; i += 256) {
        const int row = i >> 3, q = i & 7;
        const int off = row * 144 + q * 16;
        *(uint4*)(sm + off)         = qh[i];
        *(uint4*)(sm + 18432 + off) = ql[i];
    }
    for (int i = tid; i < 2048; i += 256) {
        const int row = i >> 3, q = i & 7;
        const int off = row * 144 + q * 16;
        *(uint4*)(sm + 36864 + off) = kh[i];
        *(uint4*)(sm + 73728 + off) = kl[i];
    }
    __syncthreads();

    const uint32_t sb = smem_to_u32(sm);
    const int ar = (wid >> 1) * 32, bc = (wid & 1) * 64;
    float* C = attn + (size_t)bh * Nn * Nn;
    const float S = 0.125f * 1.4426950408889634f;  // scale * log2(e)

    #pragma unroll
    for (int jhalf = 0; jhalf < 2; jhalf++) {
        const int pi = blockIdx.x * 2 + jhalf;
        float acc[2][8][4] = {};
        mma_block3(acc, sb, sb + 18432,
                   sb + 36864 + jhalf * 18432, sb + 73728 + jhalf * 18432,
                   ar, bc, lane);

        #pragma unroll
        for (int t = 0; t < 2; t++)
            #pragma unroll
            for (int nt = 0; nt < 8; nt++)
                #pragma unroll
                for (int e = 0; e < 4; e++)
                    acc[t][nt][e] *= S;

        // warp-half row max -> smax
        #pragma unroll
        for (int t = 0; t < 2; t++) {
            float mA = -1e30f, mB = -1e30f;
            #pragma unroll
            for (int nt = 0; nt < 8; nt++) {
                mA = fmaxf(mA, fmaxf(acc[t][nt][0], acc[t][nt][1]));
                mB = fmaxf(mB, fmaxf(acc[t][nt][2], acc[t][nt][3]));
            }
            mA = fmaxf(mA, __shfl_xor_sync(0xffffffffu, mA, 1));
            mA = fmaxf(mA, __shfl_xor_sync(0xffffffffu, mA, 2));
            mB = fmaxf(mB, __shfl_xor_sync(0xffffffffu, mB, 1));
            mB = fmaxf(mB, __shfl_xor_sync(0xffffffffu, mB, 2));
            if ((lane & 3) == 0) {
                const int rl = ar + t * 16 + (lane >> 2);
                smax[rl][wid & 1]     = mA;
                smax[rl + 8][wid & 1] = mB;
            }
        }
        __syncthreads();

        // single exp2 per element (inline max combine): write e + tile sums
        #pragma unroll
        for (int t = 0; t < 2; t++) {
            const int rl = ar + t * 16 + (lane >> 2);
            const float m0 = fmaxf(smax[rl][0], smax[rl][1]);
            const float m1 = fmaxf(smax[rl + 8][0], smax[rl + 8][1]);
            const int r0 = i0 + rl;
            float sA = 0.f, sB = 0.f;
            #pragma unroll
            for (int nt = 0; nt < 8; nt++) {
                const int c0 = pi * 128 + bc + nt * 8 + (lane & 3) * 2;
                const float e0 = exp2f(acc[t][nt][0] - m0);
                const float e1 = exp2f(acc[t][nt][1] - m0);
                const float e2 = exp2f(acc[t][nt][2] - m1);
                const float e3 = exp2f(acc[t][nt][3] - m1);
                *(float2*)&C[(size_t)r0 * Nn + c0]       = make_float2(e0, e1);
                *(float2*)&C[(size_t)(r0 + 8) * Nn + c0] = make_float2(e2, e3);
                sA += e0 + e1;
                sB += e2 + e3;
            }
            sA += __shfl_xor_sync(0xffffffffu, sA, 1);
            sA += __shfl_xor_sync(0xffffffffu, sA, 2);
            sB += __shfl_xor_sync(0xffffffffu, sB, 1);
            sB += __shfl_xor_sync(0xffffffffu, sB, 2);
            if ((lane & 3) == 0) {
                ssum[rl][wid & 1]     = sA;
                ssum[rl + 8][wid & 1] = sB;
            }
        }
        __syncthreads();
        if (tid < 128)
            g_part[((size_t)bh * Nn + i0 + tid) * 16 + pi] =
                make_float2(fmaxf(smax[tid][0], smax[tid][1]),
                            ssum[tid][0] + ssum[tid][1]);
        if (jhalf == 0) __syncthreads();   // protect smax/ssum reuse
    }
}

// ---------------------------------------------------------------------------
// Kernel 3b: fold partials -> per-(row,jt) scale = exp2(m_jt - m_row)/rowsum
// ---------------------------------------------------------------------------
__global__ __launch_bounds__(256) void rowstat_kernel()
{
    const int row = blockIdx.x * 256 + threadIdx.x;
    float2 p[16];
    #pragma unroll
    for (int t = 0; t < 16; t++) p[t] = g_part[(size_t)row * 16 + t];
    float m = -1e30f;
    #pragma unroll
    for (int t = 0; t < 16; t++) m = fmaxf(m, p[t].x);
    float s = 0.f;
    #pragma unroll
    for (int t = 0; t < 16; t++) s += p[t].y * exp2f(p[t].x - m);
    const float inv = 1.0f / s;
    #pragma unroll
    for (int t = 0; t < 16; t++)
        g_scale[(size_t)row * 16 + t] = exp2f(p[t].x - m) * inv;
}

// ---------------------------------------------------------------------------
// Kernel 5: AV. All 16 A-LDGs hoisted to chunk top (one DRAM-latency
// exposure per chunk, overlapped by next-B cp.async issue). Scaled probs
// written back to attn, bf16-split in regs, 3-pass HMMA vs double-buffered
// V^T. grid (16,1,32), 256 thr, 2 CTAs/SM.
// dyn smem 81920: Bh0 0  Bl0 18432  Bh1 36864  Bl1 55296  scales 73728 (8KB)
// ---------------------------------------------------------------------------
__global__ __launch_bounds__(256, 2) void av_mma_kernel(float* __restrict__ attn)
{
    extern __shared__ char sm[];
    const int tid = threadIdx.x, lane = tid & 31, wid = tid >> 5;
    const int bh = blockIdx.z;
    const int b = bh >> 3, h = bh & 7;
    const int i0 = blockIdx.x * 128;
    const uint32_t sb = smem_to_u32(sm);
    float* s_scale = (float*)(sm + 73728);

    for (int i = tid; i < 2048; i += 256)
        s_scale[i] = g_scale[((size_t)bh * Nn + i0) * 16 + i];

    auto issueB = [&](int ic2, int st2) {
        const char* vh = (const char*)(g_vth + (size_t)(b * 32 + ic2) * 4096);
        const char* vl = (const char*)(g_vtl + (size_t)(b * 32 + ic2) * 4096);
        const uint32_t base = sb + (uint32_t)st2 * 36864u;
        for (int i = tid; i < 1024; i += 256) {
            const int row = i >> 3, q = i & 7;
            const uint32_t off = (uint32_t)(row * 144 + q * 16);
            CP_ASYNC16(base + off, vh + i * 16);
            CP_ASYNC16(base + 18432 + off, vl + i * 16);
        }
    };

    issueB(0, 0);
    CP_ASYNC_WAIT_ALL();
    __syncthreads();

    float* A0 = attn + ((size_t)bh * Nn + i0) * Nn;
    const int ar = wid * 16;
    const int r = lane >> 2, c0 = (lane & 3) * 2;
    const uint32_t brow  = (uint32_t)((lane & 7) + ((lane >> 4) << 3));
    const uint32_t bcolb = (uint32_t)(((lane >> 3) & 1) * 16);

    float* Ar0 = A0 + (size_t)(ar + r) * Nn;
    float* Ar8 = Ar0 + 8 * Nn;

    float acc[16][4] = {};
    for (int ic = 0; ic < 32; ic++) {
        const int st = ic & 1;
        const int jt = ic >> 1;
        float* a0 = Ar0 + ic * 64;
        float* a8 = Ar8 + ic * 64;

        // all 16 A loads issued upfront (single latency exposure)
        float2 vv[4][4];
        #pragma unroll
        for (int ks2 = 0; ks2 < 4; ks2++) {
            const int kc = ks2 * 16 + c0;
            vv[ks2][0] = *(const float2*)(a0 + kc);
            vv[ks2][1] = *(const float2*)(a8 + kc);
            vv[ks2][2] = *(const float2*)(a0 + kc + 8);
            vv[ks2][3] = *(const float2*)(a8 + kc + 8);
        }
        // cp.async issue overlaps A-load latency
        if (ic + 1 < 32) issueB(ic + 1, 1 - st);

        const uint32_t Bh = sb + (uint32_t)st * 36864u;
        const uint32_t Bl = Bh + 18432u;
        const float sc0 = s_scale[(ar + r) * 16 + jt];
        const float sc1 = s_scale[(ar + r + 8) * 16 + jt];

        #pragma unroll
        for (int ksl = 0; ksl < 4; ksl++) {
            float2 v00 = vv[ksl][0], v10 = vv[ksl][1];
            float2 v01 = vv[ksl][2], v11 = vv[ksl][3];
            v00.x *= sc0; v00.y *= sc0; v01.x *= sc0; v01.y *= sc0;
            v10.x *= sc1; v10.y *= sc1; v11.x *= sc1; v11.y *= sc1;
            const int kc = ksl * 16 + c0;
            *(float2*)(a0 + kc)     = v00;
            *(float2*)(a8 + kc)     = v10;
            *(float2*)(a0 + kc + 8) = v01;
            *(float2*)(a8 + kc + 8) = v11;
            uint32_t ah[4], al[4];
            split2(v00, ah[0], al[0]);
            split2(v10, ah[1], al[1]);
            split2(v01, ah[2], al[2]);
            split2(v11, ah[3], al[3]);
            #pragma unroll
            for (int p = 0; p < 8; p++) {
                uint32_t bb[4];
                ldsm4(bb, Bh + (uint32_t)(p * 16 + brow) * 144u + ksl * 32u + bcolb);
                mma16816(acc[2 * p],     ah, bb[0], bb[1]);
                mma16816(acc[2 * p + 1], ah, bb[2], bb[3]);
                mma16816(acc[2 * p],     al, bb[0], bb[1]);
                mma16816(acc[2 * p + 1], al, bb[2], bb[3]);
            }
            #pragma unroll
            for (int p = 0; p < 8; p++) {
                uint32_t bb[4];
                ldsm4(bb, Bl + (uint32_t)(p * 16 + brow) * 144u + ksl * 32u + bcolb);
                mma16816(acc[2 * p],     ah, bb[0], bb[1]);
                mma16816(acc[2 * p + 1], ah, bb[2], bb[3]);
            }
        }
        CP_ASYNC_WAIT_ALL();
        __syncthreads();
    }

    float* O = g_o992 + (size_t)b * Nn * OUTF + (size_t)h * VD;
    const int r0 = i0 + ar + r;
    #pragma unroll
    for (int nt = 0; nt < 16; nt++) {
        const int cc = nt * 8 + c0;
        if (cc < VD) {
            *(float2*)&O[(size_t)r0 * OUTF + cc] =
                make_float2(acc[nt][0], acc[nt][1]);
            *(float2*)&O[(size_t)(r0 + 8) * OUTF + cc] =
                make_float2(acc[nt][2], acc[nt][3]);
        }
    }
}

// ---------------------------------------------------------------------------
// Kernel 6: out = out992 @ W_out^T + b_out
// ---------------------------------------------------------------------------
__global__ __launch_bounds__(256) void outproj_kernel(
    const float* __restrict__ Wout, const float* __restrict__ bout,
    float* __restrict__ out)
{
    __shared__ float As[16][68];
    __shared__ float Bs[16][68];
    const int i0 = blockIdx.x * 64;
    const int tid = threadIdx.x;
    const int tx = tid & 15, ty = tid >> 4;

    float acc[4][4] = {};
    for (int k0 = 0; k0 < OUTF; k0 += 16) {
        const int r  = tid >> 2;
        const int kq = (tid & 3) << 2;
        float4 a = *(const float4*)&g_o992[(size_t)(i0 + r) * OUTF + k0 + kq];
        As[kq + 0][r] = a.x; As[kq + 1][r] = a.y;
        As[kq + 2][r] = a.z; As[kq + 3][r] = a.w;
        float4 w = *(const float4*)&Wout[(size_t)r * OUTF + k0 + kq];
        Bs[kq + 0][r] = w.x; Bs[kq + 1][r] = w.y;
        Bs[kq + 2][r] = w.z; Bs[kq + 3][r] = w.w;
        __syncthreads();
        #pragma unroll
        for (int kk = 0; kk < 16; kk++) {
            float av[4], bv[4];
            *(float4*)av = *(const float4*)&As[kk][ty * 4];
            *(float4*)bv = *(const float4*)&Bs[kk][tx * 4];
            #pragma unroll
            for (int m = 0; m < 4; m++)
                #pragma unroll
                for (int n = 0; n < 4; n++)
                    acc[m][n] = fmaf(av[m], bv[n], acc[m][n]);
        }
        __syncthreads();
    }

    #pragma unroll
    for (int m = 0; m < 4; m++) {
        const int r = i0 + ty * 4 + m;
        float4 v = make_float4(acc[m][0] + bout[tx * 4 + 0],
                               acc[m][1] + bout[tx * 4 + 1],
                               acc[m][2] + bout[tx * 4 + 2],
                               acc[m][3] + bout[tx * 4 + 3]);
        *(float4*)&out[(size_t)r * Dd + tx * 4] = v;
    }
}

// ---------------------------------------------------------------------------
extern "C" void kernel_launch(void* const* d_in, const int* in_sizes, int n_in,
                              void* d_out, int out_size)
{
    const float* x    = (const float*)d_in[0];
    const float* Wqk  = (const float*)d_in[1];
    const float* w1   = (const float*)d_in[2];
    const float* b1   = (const float*)d_in[3];
    const float* w2   = (const float*)d_in[4];
    const float* b2   = (const float*)d_in[5];
    const float* Wout = (const float*)d_in[6];
    const float* bout = (const float*)d_in[7];

    float* out  = (float*)d_out;
    float* attn = out + ATTN_OFF;

    cudaFuncSetAttribute(dots_mma_kernel,
                         cudaFuncAttributeMaxDynamicSharedMemorySize, 110592);
    cudaFuncSetAttribute(av_mma_kernel,
                         cudaFuncAttributeMaxDynamicSharedMemorySize, 81920);

    qk_proj_kernel<<<dim3(BN / 64, 1024 / 64), 256>>>(x, Wqk);
    conv_kernel<<<BN / 8, 256>>>(x, w1, b1, w2, b2);
    vconv_kernel<<<Bz * 32, 256>>>();
    dots_mma_kernel<<<dim3(Nn / 256, Nn / 128, Bz * Hh), 256, 110592>>>(attn);
    rowstat_kernel<<<NROWS / 256, 256>>>();
    av_mma_kernel<<<dim3(Nn / 128, 1, Bz * Hh), 256, 81920>>>(attn);
    outproj_kernel<<<BN / 64, 256>>>(Wout, bout, out);
}